// round 13
// baseline (speedup 1.0000x reference)
#include <cuda_runtime.h>
#include <cuda_fp16.h>
#include <stdint.h>

#define Nn 50000
#define Ee 250000
#define Hh 128
#define NH (Nn*Hh)
#define EPSf 1e-5f

// ---------------- device scratch (static, no allocs) ----------------
__device__ float  g_h[NH];           // node features (h0 -> h1 -> h2)
__device__ float  g_xw[2*NH];        // xs per relation (dinv-scaled gemm out)
__device__ __half g_pqh[4*NH];       // Pb, Qb, Pc, Qc in fp16
__device__ int    g_degi[2*Nn];      // in-degree per relation
__device__ int    g_off[2*(Nn+1)];   // CSR offsets per relation
__device__ int    g_cursor[2*Nn];    // fill cursors
__device__ int    g_eis[2*Ee];       // int32 src per relation
__device__ int    g_eid[2*Ee];       // int32 dst per relation
__device__ int    g_csr[2*Ee];       // CSR src lists
__device__ float  g_stats[1024];     // enc sums [0:256), beam [256:512), col [512:768)
__device__ float  g_wp[2][Hh*2];     // folded BN*Wbp2 per relation
__device__ float  g_bp[2][2];        // folded bias per relation
__device__ int    g_is64;

// ---------------- helpers ----------------
__device__ __forceinline__ long long ld_idx(const void* p, long long i, int is64) {
    return is64 ? ((const long long*)p)[i] : (long long)((const int*)p)[i];
}

__device__ __forceinline__ uint32_t tf32_rna(float x) {
    uint32_t r;
    asm("cvt.rna.tf32.f32 %0, %1;" : "=r"(r) : "f"(x));
    return r;
}

__device__ __forceinline__ void mma_tf32(float* d, const uint32_t* a, const uint32_t* b) {
    asm volatile(
        "mma.sync.aligned.m16n8k8.row.col.f32.tf32.tf32.f32 "
        "{%0,%1,%2,%3}, {%4,%5,%6,%7}, {%8,%9}, {%0,%1,%2,%3};"
        : "+f"(d[0]), "+f"(d[1]), "+f"(d[2]), "+f"(d[3])
        : "r"(a[0]), "r"(a[1]), "r"(a[2]), "r"(a[3]), "r"(b[0]), "r"(b[1]));
}

// split one fp32 into tf32 hi/lo (registers)
__device__ __forceinline__ void split_tf32(float x, uint32_t& h, uint32_t& l) {
    h = tf32_rna(x);
    l = tf32_rna(x - __uint_as_float(h));
}

// ---------------- mma.sync 3xTF32 GEMM (fp32 smem, split at frag load) ----------------
// C[y][M,128] = op(A)[M,128] @ W[y][128,128]  (row-major)
// op(A): optional per-column BN affine computed IN-KERNEL from g_stats (gEnc!=null).
// Epilogue: optional per-row scale rsqrt(deg[r]+1); optional fp16 output (halfOut).
#define APAD 36
#define BPAD 136
#define B_OFF (128*APAD)
#define AC_OFF (B_OFF + 32*BPAD)
#define SMEM_MM ((AC_OFF + 256) * 4)

__global__ void __launch_bounds__(256, 2)
k_mma(const float* __restrict__ A,
      const float* __restrict__ W0, const float* __restrict__ W1,
      const float* __restrict__ W2, const float* __restrict__ W3,
      void* __restrict__ C0, void* __restrict__ C1,
      void* __restrict__ C2, void* __restrict__ C3,
      const int* __restrict__ D0, const int* __restrict__ D1,
      const float* __restrict__ gEnc, const float* __restrict__ beEnc,
      int halfOut, int M) {
    extern __shared__ float smf[];
    float* As = smf;                          // [128][APAD] fp32
    float* Bs = smf + B_OFF;                  // [32][BPAD]  fp32
    float* acs = smf + AC_OFF;                // [256] BN affine a|c

    int tid = threadIdx.x;
    int lane = tid & 31, wid = tid >> 5;
    int wm = wid >> 1, wn = wid & 1;          // warp grid 4x2
    int m0 = blockIdx.x * 128;
    int qt = lane >> 2;                       // 0..7
    int qr = lane & 3;                        // 0..3

    const float* W = (blockIdx.y == 0) ? W0 : (blockIdx.y == 1) ? W1 : (blockIdx.y == 2) ? W2 : W3;
    void* Cv = (blockIdx.y == 0) ? C0 : (blockIdx.y == 1) ? C1 : (blockIdx.y == 2) ? C2 : C3;
    const int* DG = (blockIdx.y == 0) ? D0 : (blockIdx.y == 1) ? D1 : nullptr;

    uint32_t bs_bytes;
    {
        uint64_t t;
        asm("cvta.to.shared.u64 %0, %1;" : "=l"(t) : "l"(Bs));
        bs_bytes = (uint32_t)t;
    }

    if (gEnc && tid < 128) {
        float m = g_stats[tid] * (1.0f / Nn);
        float v = g_stats[128 + tid] * (1.0f / Nn) - m * m;
        float a = gEnc[tid] * rsqrtf(v + EPSf);
        acs[tid] = a;
        acs[128 + tid] = beEnc[tid] - a * m;
    }
    __syncthreads();

    float acc[2][8][4];
#pragma unroll
    for (int i = 0; i < 2; i++)
#pragma unroll
        for (int j = 0; j < 8; j++)
#pragma unroll
            for (int q = 0; q < 4; q++) acc[i][j][q] = 0.f;

    for (int ch = 0; ch < 4; ch++) {
        int k0 = ch * 32;
        if (ch > 0) __syncthreads();
        // ---- B fill via cp.async (16KB: rows k0..k0+31 x 128 fp32) ----
#pragma unroll
        for (int rep = 0; rep < 4; rep++) {
            int idx = tid + rep * 256;            // 0..1023
            int kk = idx >> 5;                    // 0..31
            int n4 = (idx & 31) * 4;              // 0..124
            uint32_t dst = bs_bytes + (kk * BPAD + n4) * 4;
            const float* src = W + (size_t)(k0 + kk) * 128 + n4;
            asm volatile("cp.async.cg.shared.global [%0], [%1], 16;" :: "r"(dst), "l"(src));
        }
        asm volatile("cp.async.commit_group;");
        // ---- A fill [128 rows x 32 k] fp32 (optional BN affine) ----
#pragma unroll
        for (int rep = 0; rep < 4; rep++) {
            int i4 = tid + rep * 256;             // 0..1023 float4s
            int r = i4 >> 3;                      // row 0..127
            int c = (i4 & 7) * 4;                 // k 0..28
            float4 v = make_float4(0.f, 0.f, 0.f, 0.f);
            if (m0 + r < M) v = *(const float4*)(A + (size_t)(m0 + r) * 128 + k0 + c);
            if (gEnc) {
                float4 a4 = *(const float4*)(acs + k0 + c);
                float4 c4 = *(const float4*)(acs + 128 + k0 + c);
                v.x = fmaf(a4.x, v.x, c4.x);
                v.y = fmaf(a4.y, v.y, c4.y);
                v.z = fmaf(a4.z, v.z, c4.z);
                v.w = fmaf(a4.w, v.w, c4.w);
            }
            *(float4*)(As + r * APAD + c) = v;
        }
        asm volatile("cp.async.wait_group 0;");
        __syncthreads();
        // ---- compute 4 k-steps of 8 (split to tf32 hi/lo in registers) ----
#pragma unroll
        for (int s = 0; s < 4; s++) {
            int kc = s * 8 + qr;
            uint32_t ah[2][4], al[2][4];
#pragma unroll
            for (int mf = 0; mf < 2; mf++) {
                int r0 = wm * 32 + mf * 16 + qt;
                float a0 = As[r0 * APAD + kc];
                float a1 = As[(r0 + 8) * APAD + kc];
                float a2 = As[r0 * APAD + kc + 4];
                float a3 = As[(r0 + 8) * APAD + kc + 4];
                split_tf32(a0, ah[mf][0], al[mf][0]);
                split_tf32(a1, ah[mf][1], al[mf][1]);
                split_tf32(a2, ah[mf][2], al[mf][2]);
                split_tf32(a3, ah[mf][3], al[mf][3]);
            }
            uint32_t bh[8][2], bl[8][2];
#pragma unroll
            for (int nf = 0; nf < 8; nf++) {
                int cn = wn * 64 + nf * 8 + qt;
                float b0 = Bs[kc * BPAD + cn];
                float b1 = Bs[(kc + 4) * BPAD + cn];
                split_tf32(b0, bh[nf][0], bl[nf][0]);
                split_tf32(b1, bh[nf][1], bl[nf][1]);
            }
#pragma unroll
            for (int mf = 0; mf < 2; mf++)
#pragma unroll
                for (int nf = 0; nf < 8; nf++) {
                    mma_tf32(acc[mf][nf], ah[mf], bh[nf]);
                    mma_tf32(acc[mf][nf], ah[mf], bl[nf]);
                    mma_tf32(acc[mf][nf], al[mf], bh[nf]);
                }
        }
    }
    // ---- epilogue (optional per-row dinv scale, optional fp16 out) ----
#pragma unroll
    for (int mf = 0; mf < 2; mf++) {
        int r = m0 + wm * 32 + mf * 16 + qt;
        float sc0 = 1.f, sc1 = 1.f;
        if (DG) {
            if (r < M) sc0 = rsqrtf((float)DG[r] + 1.f);
            if (r + 8 < M) sc1 = rsqrtf((float)DG[r + 8] + 1.f);
        }
#pragma unroll
        for (int nf = 0; nf < 8; nf++) {
            int cc = wn * 64 + nf * 8 + qr * 2;
            if (halfOut) {
                __half* CH = (__half*)Cv;
                if (r < M)
                    *(__half2*)(CH + (size_t)r * 128 + cc) =
                        __floats2half2_rn(sc0 * acc[mf][nf][0], sc0 * acc[mf][nf][1]);
                if (r + 8 < M)
                    *(__half2*)(CH + (size_t)(r + 8) * 128 + cc) =
                        __floats2half2_rn(sc1 * acc[mf][nf][2], sc1 * acc[mf][nf][3]);
            } else {
                float* C = (float*)Cv;
                if (r < M)
                    *(float2*)(C + (size_t)r * 128 + cc) =
                        make_float2(sc0 * acc[mf][nf][0], sc0 * acc[mf][nf][1]);
                if (r + 8 < M)
                    *(float2*)(C + (size_t)(r + 8) * 128 + cc) =
                        make_float2(sc1 * acc[mf][nf][2], sc1 * acc[mf][nf][3]);
            }
        }
    }
}

// ---------------- graph prep ----------------

__global__ void k_zero(const int* w) {
    int i = blockIdx.x * blockDim.x + threadIdx.x;
    if (i < 2 * Nn) g_degi[i] = 0;
    if (i < 1024) g_stats[i] = 0.f;
    if (blockIdx.x == 0) {
        __shared__ int anynz;
        if (threadIdx.x == 0) anynz = 0;
        __syncthreads();
        if (w[threadIdx.x * 2 + 1] != 0) atomicExch(&anynz, 1);
        __syncthreads();
        if (threadIdx.x == 0) g_is64 = (anynz == 0) ? 1 : 0;
    }
}

__global__ void k_cvt_deg(const void* __restrict__ beam, const void* __restrict__ col) {
    int t = blockIdx.x * blockDim.x + threadIdx.x;
    if (t >= 2 * Ee) return;
    int rel = (t >= Ee) ? 1 : 0;
    int e = t - rel * Ee;
    const void* ei = rel ? col : beam;
    int is64 = g_is64;
    int s = (int)ld_idx(ei, e, is64);
    int d = (int)ld_idx(ei, (long long)Ee + e, is64);
    g_eis[rel * Ee + e] = s;
    g_eid[rel * Ee + e] = d;
    atomicAdd(&g_degi[rel * Nn + d], 1);
}

// exclusive scan: 1024 threads x 49 serial nodes, one block-wide scan
#define SCH 49
__global__ void __launch_bounds__(1024) k_scan() {
    __shared__ int sh[1024];
    int tid = threadIdx.x;
    for (int rel = 0; rel < 2; rel++) {
        const int* deg = g_degi + rel * Nn;
        int* off = g_off + rel * (Nn + 1);
        int* cur = g_cursor + rel * Nn;
        int start = tid * SCH;
        int s = 0;
        int dl[SCH];
#pragma unroll
        for (int i = 0; i < SCH; i++) {
            int idx = start + i;
            dl[i] = (idx < Nn) ? deg[idx] : 0;
            s += dl[i];
        }
        sh[tid] = s;
        __syncthreads();
#pragma unroll
        for (int o = 1; o < 1024; o <<= 1) {
            int t = (tid >= o) ? sh[tid - o] : 0;
            __syncthreads();
            sh[tid] += t;
            __syncthreads();
        }
        int run = sh[tid] - s;   // exclusive prefix
#pragma unroll
        for (int i = 0; i < SCH; i++) {
            int idx = start + i;
            if (idx < Nn) {
                off[idx] = run;
                cur[idx] = run;
                run += dl[i];
            }
        }
        if (tid == 1023) off[Nn] = run;
        __syncthreads();
    }
}

__global__ void k_fill() {
    int t = blockIdx.x * blockDim.x + threadIdx.x;
    if (t >= 2 * Ee) return;
    int rel = (t >= Ee) ? 1 : 0;
    int e = t - rel * Ee;
    int d = g_eid[rel * Ee + e];
    int pos = atomicAdd(&g_cursor[rel * Nn + d], 1);
    g_csr[rel * Ee + pos] = g_eis[rel * Ee + e];
}

// ---------------- node encoder (smem-staged x, R11-proven) ----------------
__global__ void __launch_bounds__(128) k_encoder(const float* __restrict__ x,
                                                 const float* __restrict__ W,
                                                 const float* __restrict__ b) {
    __shared__ float sx[384];
    int c = threadIdx.x;
    int n0 = blockIdx.x * 128;
    float w0 = W[c], w1 = W[Hh + c], w2 = W[2 * Hh + c], bb = b[c];
#pragma unroll
    for (int i = c; i < 384; i += 128) {
        int gidx = n0 * 3 + i;
        sx[i] = (gidx < Nn * 3) ? x[gidx] : 0.f;
    }
    __syncthreads();
    int lim = Nn - n0; if (lim > 128) lim = 128;
    float s = 0.f, s2 = 0.f;
    for (int j = 0; j < lim; j++) {
        float v = fmaxf(fmaf(sx[3 * j + 2], w2, fmaf(sx[3 * j + 1], w1, fmaf(sx[3 * j], w0, bb))), 0.f);
        g_h[(size_t)(n0 + j) * 128 + c] = v;
        s += v; s2 += v * v;
    }
    atomicAdd(&g_stats[c], s);
    atomicAdd(&g_stats[Hh + c], s2);
}

// ---------------- fused GCN aggregation (CSR gather, 4x unrolled) ----------------
__global__ void k_agg(const float* __restrict__ bias_b, const float* __restrict__ bias_c,
                      int dorelu) {
    int gt = blockIdx.x * blockDim.x + threadIdx.x;
    int d = gt >> 5;
    if (d >= Nn) return;
    int l4 = (gt & 31) * 4;

    float4 o = make_float4(0.f, 0.f, 0.f, 0.f);
#pragma unroll
    for (int rel = 0; rel < 2; rel++) {
        const float* xs = g_xw + rel * NH;
        const int* csr = g_csr + rel * Ee;
        float4 acc = *(const float4*)(xs + (size_t)d * 128 + l4);
        int e = g_off[rel * (Nn + 1) + d];
        int end = g_off[rel * (Nn + 1) + d + 1];
        for (; e + 4 <= end; e += 4) {
            int s0 = csr[e], s1 = csr[e + 1], s2 = csr[e + 2], s3 = csr[e + 3];
            float4 v0 = *(const float4*)(xs + (size_t)s0 * 128 + l4);
            float4 v1 = *(const float4*)(xs + (size_t)s1 * 128 + l4);
            float4 v2 = *(const float4*)(xs + (size_t)s2 * 128 + l4);
            float4 v3 = *(const float4*)(xs + (size_t)s3 * 128 + l4);
            acc.x += v0.x + v1.x + v2.x + v3.x;
            acc.y += v0.y + v1.y + v2.y + v3.y;
            acc.z += v0.z + v1.z + v2.z + v3.z;
            acc.w += v0.w + v1.w + v2.w + v3.w;
        }
        for (; e < end; e++) {
            int s = csr[e];
            float4 v = *(const float4*)(xs + (size_t)s * 128 + l4);
            acc.x += v.x; acc.y += v.y; acc.z += v.z; acc.w += v.w;
        }
        float dv = rsqrtf((float)g_degi[rel * Nn + d] + 1.f);
        o.x = fmaf(dv, acc.x, o.x);
        o.y = fmaf(dv, acc.y, o.y);
        o.z = fmaf(dv, acc.z, o.z);
        o.w = fmaf(dv, acc.w, o.w);
    }
    float4 bb = *(const float4*)(bias_b + l4);
    float4 bc = *(const float4*)(bias_c + l4);
    o.x += bb.x + bc.x; o.y += bb.y + bc.y;
    o.z += bb.z + bc.z; o.w += bb.w + bc.w;
    if (dorelu) {
        o.x = fmaxf(o.x, 0.f); o.y = fmaxf(o.y, 0.f);
        o.z = fmaxf(o.z, 0.f); o.w = fmaxf(o.w, 0.f);
    }
    *(float4*)(g_h + (size_t)d * 128 + l4) = o;
}

// ---------------- edge predictors (fp16 P/Q) ----------------

__device__ __forceinline__ float4 ld_pq4(const __half* base, int row, int l4) {
    const __half2* p2 = (const __half2*)(base + (size_t)row * 128 + l4);
    float2 a = __half22float2(p2[0]);
    float2 b = __half22float2(p2[1]);
    return make_float4(a.x, a.y, b.x, b.y);
}

__global__ void k_edge_stats(const __half* __restrict__ Pb, const __half* __restrict__ Qb,
                             const float* __restrict__ bb,
                             const __half* __restrict__ Pc, const __half* __restrict__ Qc,
                             const float* __restrict__ bc) {
    int rel = blockIdx.y;
    const __half* P = rel ? Pc : Pb;
    const __half* Q = rel ? Qc : Qb;
    const float* bias = rel ? bc : bb;
    const int* es = g_eis + rel * Ee;
    const int* ed = g_eid + rel * Ee;
    float* sum = g_stats + 256 + rel * 256;
    float* sq = sum + 128;

    int lane = threadIdx.x & 31;
    int warp = (blockIdx.x * blockDim.x + threadIdx.x) >> 5;
    int nw = (gridDim.x * blockDim.x) >> 5;
    int l4 = lane * 4;
    float4 b = ((const float4*)bias)[lane];
    float4 s = make_float4(0.f, 0.f, 0.f, 0.f);
    float4 s2 = make_float4(0.f, 0.f, 0.f, 0.f);
    for (int e = warp; e < Ee; e += nw) {
        int si = es[e], di = ed[e];
        float4 p = ld_pq4(P, si, l4);
        float4 q = ld_pq4(Q, di, l4);
        float4 z;
        z.x = fmaxf(p.x + q.x + b.x, 0.f);
        z.y = fmaxf(p.y + q.y + b.y, 0.f);
        z.z = fmaxf(p.z + q.z + b.z, 0.f);
        z.w = fmaxf(p.w + q.w + b.w, 0.f);
        s.x += z.x; s.y += z.y; s.z += z.z; s.w += z.w;
        s2.x += z.x * z.x; s2.y += z.y * z.y; s2.z += z.z * z.z; s2.w += z.w * z.w;
    }
    int c = lane * 4;
    atomicAdd(&sum[c + 0], s.x); atomicAdd(&sum[c + 1], s.y);
    atomicAdd(&sum[c + 2], s.z); atomicAdd(&sum[c + 3], s.w);
    atomicAdd(&sq[c + 0], s2.x); atomicAdd(&sq[c + 1], s2.y);
    atomicAdd(&sq[c + 2], s2.z); atomicAdd(&sq[c + 3], s2.w);
}

__global__ void k_bn_pred(const float* gb, const float* beb, const float* W2b, const float* b2b,
                          const float* gc, const float* bec, const float* W2c, const float* b2c) {
    __shared__ float r0s[Hh], r1s[Hh];
    int k = threadIdx.x;
    for (int rel = 0; rel < 2; rel++) {
        const float* g  = rel ? gc  : gb;
        const float* be = rel ? bec : beb;
        const float* W2 = rel ? W2c : W2b;
        const float* b2 = rel ? b2c : b2b;
        const float* sum = &g_stats[256 + rel * 256];
        const float* sq  = &g_stats[256 + rel * 256 + 128];
        float m = sum[k] * (1.0f / Ee);
        float v = sq[k] * (1.0f / Ee) - m * m;
        float a = g[k] * rsqrtf(v + EPSf);
        float cc = be[k] - a * m;
        float w0 = W2[k * 2], w1 = W2[k * 2 + 1];
        g_wp[rel][k * 2] = a * w0;
        g_wp[rel][k * 2 + 1] = a * w1;
        r0s[k] = cc * w0;
        r1s[k] = cc * w1;
        __syncthreads();
        for (int off = 64; off > 0; off >>= 1) {
            if (k < off) { r0s[k] += r0s[k + off]; r1s[k] += r1s[k + off]; }
            __syncthreads();
        }
        if (k == 0) {
            g_bp[rel][0] = r0s[0] + b2[0];
            g_bp[rel][1] = r1s[0] + b2[1];
        }
        __syncthreads();
    }
}

__global__ void k_pred(const __half* __restrict__ Pb, const __half* __restrict__ Qb,
                       const float* __restrict__ bb,
                       const __half* __restrict__ Pc, const __half* __restrict__ Qc,
                       const float* __restrict__ bc, float* __restrict__ outbase) {
    int rel = blockIdx.y;
    const __half* P = rel ? Pc : Pb;
    const __half* Q = rel ? Qc : Qb;
    const float* bias = rel ? bc : bb;
    const int* es = g_eis + rel * Ee;
    const int* ed = g_eid + rel * Ee;
    float* out = outbase + (size_t)rel * 2 * Ee;

    int gt = blockIdx.x * blockDim.x + threadIdx.x;
    int e = gt >> 5;
    int lane = gt & 31;
    if (e >= Ee) return;
    int l4 = lane * 4;
    float4 b = ((const float4*)bias)[lane];
    const float* W = g_wp[rel];
    float w00 = W[(l4 + 0) * 2], w01 = W[(l4 + 0) * 2 + 1];
    float w10 = W[(l4 + 1) * 2], w11 = W[(l4 + 1) * 2 + 1];
    float w20 = W[(l4 + 2) * 2], w21 = W[(l4 + 2) * 2 + 1];
    float w30 = W[(l4 + 3) * 2], w31 = W[(l4 + 3) * 2 + 1];
    int si = es[e], di = ed[e];
    float4 p = ld_pq4(P, si, l4);
    float4 q = ld_pq4(Q, di, l4);
    float4 z;
    z.x = fmaxf(p.x + q.x + b.x, 0.f);
    z.y = fmaxf(p.y + q.y + b.y, 0.f);
    z.z = fmaxf(p.z + q.z + b.z, 0.f);
    z.w = fmaxf(p.w + q.w + b.w, 0.f);
    float s0 = z.x * w00 + z.y * w10 + z.z * w20 + z.w * w30;
    float s1 = z.x * w01 + z.y * w11 + z.z * w21 + z.w * w31;
#pragma unroll
    for (int off = 16; off > 0; off >>= 1) {
        s0 += __shfl_xor_sync(0xffffffffu, s0, off);
        s1 += __shfl_xor_sync(0xffffffffu, s1, off);
    }
    if (lane == 0) {
        float2 r = make_float2(s0 + g_bp[rel][0], s1 + g_bp[rel][1]);
        ((float2*)out)[e] = r;
    }
}

__global__ void k_etypes(float* __restrict__ out) {
    int i = blockIdx.x * blockDim.x + threadIdx.x;
    if (i < 2 * Ee) out[i] = (i < Ee) ? 0.f : 1.f;
}

// ---------------- host ----------------
extern "C" void kernel_launch(void* const* d_in, const int* in_sizes, int n_in,
                              void* d_out, int out_size) {
    (void)in_sizes; (void)n_in; (void)out_size;
    const float* x     = (const float*)d_in[0];
    const void*  beam  = d_in[1];
    const void*  col   = d_in[2];
    const float* W_enc = (const float*)d_in[3];
    const float* b_enc = (const float*)d_in[4];
    const float* g_enc = (const float*)d_in[5];
    const float* be_enc= (const float*)d_in[6];
    const float* W1b   = (const float*)d_in[7];
    const float* b1b   = (const float*)d_in[8];
    const float* W1c   = (const float*)d_in[9];
    const float* b1c   = (const float*)d_in[10];
    const float* W2b   = (const float*)d_in[11];
    const float* b2b   = (const float*)d_in[12];
    const float* W2c   = (const float*)d_in[13];
    const float* b2c   = (const float*)d_in[14];
    const float* Wbp1  = (const float*)d_in[15];
    const float* bbp1  = (const float*)d_in[16];
    const float* gbp   = (const float*)d_in[17];
    const float* bebp  = (const float*)d_in[18];
    const float* Wbp2  = (const float*)d_in[19];
    const float* bbp2  = (const float*)d_in[20];
    const float* Wcp1  = (const float*)d_in[21];
    const float* bcp1  = (const float*)d_in[22];
    const float* gcp   = (const float*)d_in[23];
    const float* becp  = (const float*)d_in[24];
    const float* Wcp2  = (const float*)d_in[25];
    const float* bcp2  = (const float*)d_in[26];
    float* out = (float*)d_out;

    float *p_h, *p_xw;
    __half* p_pq;
    int *p_deg;
    cudaGetSymbolAddress((void**)&p_h, g_h);
    cudaGetSymbolAddress((void**)&p_xw, g_xw);
    cudaGetSymbolAddress((void**)&p_pq, g_pqh);
    cudaGetSymbolAddress((void**)&p_deg, g_degi);

    cudaFuncSetAttribute(k_mma, cudaFuncAttributeMaxDynamicSharedMemorySize, SMEM_MM);

    const int GB = (Nn + 127) / 128;   // 391 M-tiles
    const int EV = Ee * 32;
    const int NW = Nn * 32;

    k_zero<<<(2 * Nn + 255) / 256, 256>>>((const int*)beam);                 // 1
    k_cvt_deg<<<(2 * Ee + 255) / 256, 256>>>(beam, col);                     // 2
    k_encoder<<<GB, 128>>>(x, W_enc, b_enc);                                 // 3

    // GCN layer 1: xs_rel = dinv_rel * (bnaffine(h0) @ W1_rel)              // 4 <- profiled
    k_mma<<<dim3(GB, 2), 256, SMEM_MM>>>(p_h, W1b, W1c, W1b, W1b,
                                         p_xw, p_xw + NH, p_xw, p_xw,
                                         p_deg, p_deg + Nn,
                                         g_enc, be_enc, 0, Nn);
    k_scan<<<1, 1024>>>();                                                   // 5
    k_fill<<<(2 * Ee + 255) / 256, 256>>>();                                 // 6
    k_agg<<<(NW + 255) / 256, 256>>>(b1b, b1c, 1);                           // 7

    // GCN layer 2
    k_mma<<<dim3(GB, 2), 256, SMEM_MM>>>(p_h, W2b, W2c, W2b, W2b,            // 8
                                         p_xw, p_xw + NH, p_xw, p_xw,
                                         p_deg, p_deg + Nn,
                                         nullptr, nullptr, 0, Nn);
    k_agg<<<(NW + 255) / 256, 256>>>(b2b, b2c, 0);                           // 9

    // edge predictors: P/Q = h2 @ (top/bottom halves of Wbp1 / Wcp1), fp16 out
    k_mma<<<dim3(GB, 4), 256, SMEM_MM>>>(p_h, Wbp1, Wbp1 + Hh * Hh,          // 10
                                         Wcp1, Wcp1 + Hh * Hh,
                                         p_pq, p_pq + NH, p_pq + 2 * NH, p_pq + 3 * NH,
                                         nullptr, nullptr,
                                         nullptr, nullptr, 1, Nn);

    k_edge_stats<<<dim3(512, 2), 256>>>(p_pq, p_pq + NH, bbp1,               // 11
                                        p_pq + 2 * NH, p_pq + 3 * NH, bcp1);
    k_bn_pred<<<1, 128>>>(gbp, bebp, Wbp2, bbp2, gcp, becp, Wcp2, bcp2);     // 12
    k_pred<<<dim3((EV + 255) / 256, 2), 256>>>(p_pq, p_pq + NH, bbp1,        // 13
                                               p_pq + 2 * NH, p_pq + 3 * NH, bcp1, out);
    k_etypes<<<(2 * Ee + 255) / 256, 256>>>(out + 4 * Ee);                   // 14
}

// round 14
// speedup vs baseline: 1.1069x; 1.1069x over previous
#include <cuda_runtime.h>
#include <cuda_fp16.h>
#include <stdint.h>

#define Nn 50000
#define Ee 250000
#define Hh 128
#define NH (Nn*Hh)
#define EPSf 1e-5f

// ---------------- device scratch (static, no allocs) ----------------
__device__ float  g_h[NH];           // node features (h0 -> h1 -> h2)
__device__ float  g_xw[2*NH];        // xs per relation (dinv-scaled gemm out)
__device__ __half g_pqh[4*NH];       // Pb, Qb, Pc, Qc in fp16
__device__ int    g_degi[2*Nn];      // in-degree per relation
__device__ int    g_off[2*(Nn+1)];   // CSR offsets per relation
__device__ int    g_cursor[2*Nn];    // fill cursors
__device__ int    g_eis[2*Ee];       // int32 src per relation
__device__ int    g_eid[2*Ee];       // int32 dst per relation
__device__ int    g_csr[2*Ee];       // CSR src lists
__device__ float  g_stats[1024];     // enc sums [0:256), beam [256:512), col [512:768)
__device__ float  g_wp[2][Hh*2];     // folded BN*Wbp2 per relation
__device__ float  g_bp[2][2];        // folded bias per relation
__device__ int    g_is64;

// ---------------- helpers ----------------
__device__ __forceinline__ long long ld_idx(const void* p, long long i, int is64) {
    return is64 ? ((const long long*)p)[i] : (long long)((const int*)p)[i];
}

__device__ __forceinline__ uint32_t tf32_rna(float x) {
    uint32_t r;
    asm("cvt.rna.tf32.f32 %0, %1;" : "=r"(r) : "f"(x));
    return r;
}

__device__ __forceinline__ void mma_tf32(float* d, const uint32_t* a, const uint32_t* b) {
    asm volatile(
        "mma.sync.aligned.m16n8k8.row.col.f32.tf32.tf32.f32 "
        "{%0,%1,%2,%3}, {%4,%5,%6,%7}, {%8,%9}, {%0,%1,%2,%3};"
        : "+f"(d[0]), "+f"(d[1]), "+f"(d[2]), "+f"(d[3])
        : "r"(a[0]), "r"(a[1]), "r"(a[2]), "r"(a[3]), "r"(b[0]), "r"(b[1]));
}

// ---------------- mma.sync 3xTF32 GEMM (R12-proven: split at fill, LDS.32) ----------------
#define APAD 36
#define BPAD 136
#define AC_OFF (128*APAD*2 + 32*BPAD*2)
#define SMEM_MM ((AC_OFF + 256) * 4)

__global__ void __launch_bounds__(256, 2)
k_mma(const float* __restrict__ A,
      const float* __restrict__ W0, const float* __restrict__ W1,
      const float* __restrict__ W2, const float* __restrict__ W3,
      void* __restrict__ C0, void* __restrict__ C1,
      void* __restrict__ C2, void* __restrict__ C3,
      const int* __restrict__ D0, const int* __restrict__ D1,
      const float* __restrict__ gEnc, const float* __restrict__ beEnc,
      int halfOut, int M) {
    extern __shared__ uint32_t sm[];
    uint32_t* Ahi = sm;                       // [128][APAD]
    uint32_t* Alo = Ahi + 128 * APAD;
    uint32_t* Bhi = Alo + 128 * APAD;         // [32][BPAD]
    uint32_t* Blo = Bhi + 32 * BPAD;
    float* acs = (float*)(sm + AC_OFF);       // [256] BN affine a|c

    int tid = threadIdx.x;
    int lane = tid & 31, wid = tid >> 5;
    int wm = wid >> 1, wn = wid & 1;          // warp grid 4x2
    int m0 = blockIdx.x * 128;
    int qt = lane >> 2;                       // 0..7
    int qr = lane & 3;                        // 0..3

    const float* W = (blockIdx.y == 0) ? W0 : (blockIdx.y == 1) ? W1 : (blockIdx.y == 2) ? W2 : W3;
    void* Cv = (blockIdx.y == 0) ? C0 : (blockIdx.y == 1) ? C1 : (blockIdx.y == 2) ? C2 : C3;
    const int* DG = (blockIdx.y == 0) ? D0 : (blockIdx.y == 1) ? D1 : nullptr;

    if (gEnc && tid < 128) {
        float m = g_stats[tid] * (1.0f / Nn);
        float v = g_stats[128 + tid] * (1.0f / Nn) - m * m;
        float a = gEnc[tid] * rsqrtf(v + EPSf);
        acs[tid] = a;
        acs[128 + tid] = beEnc[tid] - a * m;
    }
    __syncthreads();

    float acc[2][8][4];
#pragma unroll
    for (int i = 0; i < 2; i++)
#pragma unroll
        for (int j = 0; j < 8; j++)
#pragma unroll
            for (int q = 0; q < 4; q++) acc[i][j][q] = 0.f;

    for (int ch = 0; ch < 4; ch++) {
        int k0 = ch * 32;
        if (ch > 0) __syncthreads();
        // ---- fill A chunk [128 rows x 32 k] hi/lo (optional BN affine) ----
#pragma unroll
        for (int rep = 0; rep < 4; rep++) {
            int i4 = tid + rep * 256;         // 0..1023 float4s
            int r = i4 >> 3;                  // row 0..127
            int c = (i4 & 7) * 4;             // k 0..28
            float4 v = make_float4(0.f, 0.f, 0.f, 0.f);
            if (m0 + r < M) v = *(const float4*)(A + (size_t)(m0 + r) * 128 + k0 + c);
            if (gEnc) {
                float4 a4 = *(const float4*)(acs + k0 + c);
                float4 c4 = *(const float4*)(acs + 128 + k0 + c);
                v.x = fmaf(a4.x, v.x, c4.x);
                v.y = fmaf(a4.y, v.y, c4.y);
                v.z = fmaf(a4.z, v.z, c4.z);
                v.w = fmaf(a4.w, v.w, c4.w);
            }
            uint4 h, l;
            h.x = tf32_rna(v.x); l.x = tf32_rna(v.x - __uint_as_float(h.x));
            h.y = tf32_rna(v.y); l.y = tf32_rna(v.y - __uint_as_float(h.y));
            h.z = tf32_rna(v.z); l.z = tf32_rna(v.z - __uint_as_float(h.z));
            h.w = tf32_rna(v.w); l.w = tf32_rna(v.w - __uint_as_float(h.w));
            *(uint4*)(Ahi + r * APAD + c) = h;
            *(uint4*)(Alo + r * APAD + c) = l;
        }
        // ---- fill B chunk: Bs[k][n] = W[(k0+k)*128 + n] ----
#pragma unroll
        for (int rep = 0; rep < 4; rep++) {
            int i4 = tid + rep * 256;
            int kk = i4 >> 5;                 // 0..31
            int n = (i4 & 31) * 4;            // 0..124
            float4 v = *(const float4*)(W + (size_t)(k0 + kk) * 128 + n);
            uint4 h, l;
            h.x = tf32_rna(v.x); l.x = tf32_rna(v.x - __uint_as_float(h.x));
            h.y = tf32_rna(v.y); l.y = tf32_rna(v.y - __uint_as_float(h.y));
            h.z = tf32_rna(v.z); l.z = tf32_rna(v.z - __uint_as_float(h.z));
            h.w = tf32_rna(v.w); l.w = tf32_rna(v.w - __uint_as_float(h.w));
            *(uint4*)(Bhi + kk * BPAD + n) = h;
            *(uint4*)(Blo + kk * BPAD + n) = l;
        }
        __syncthreads();
        // ---- compute 4 k-steps of 8 ----
#pragma unroll
        for (int s = 0; s < 4; s++) {
            int k = s * 8;
            uint32_t ah[2][4], al[2][4];
#pragma unroll
            for (int mf = 0; mf < 2; mf++) {
                int r0 = wm * 32 + mf * 16 + qt;
                int kc = k + qr;
                ah[mf][0] = Ahi[r0 * APAD + kc];
                ah[mf][1] = Ahi[(r0 + 8) * APAD + kc];
                ah[mf][2] = Ahi[r0 * APAD + kc + 4];
                ah[mf][3] = Ahi[(r0 + 8) * APAD + kc + 4];
                al[mf][0] = Alo[r0 * APAD + kc];
                al[mf][1] = Alo[(r0 + 8) * APAD + kc];
                al[mf][2] = Alo[r0 * APAD + kc + 4];
                al[mf][3] = Alo[(r0 + 8) * APAD + kc + 4];
            }
            uint32_t bh[8][2], bl[8][2];
#pragma unroll
            for (int nf = 0; nf < 8; nf++) {
                int cn = wn * 64 + nf * 8 + qt;
                int kr = k + qr;
                bh[nf][0] = Bhi[kr * BPAD + cn];
                bh[nf][1] = Bhi[(kr + 4) * BPAD + cn];
                bl[nf][0] = Blo[kr * BPAD + cn];
                bl[nf][1] = Blo[(kr + 4) * BPAD + cn];
            }
#pragma unroll
            for (int mf = 0; mf < 2; mf++)
#pragma unroll
                for (int nf = 0; nf < 8; nf++) {
                    mma_tf32(acc[mf][nf], ah[mf], bh[nf]);
                    mma_tf32(acc[mf][nf], ah[mf], bl[nf]);
                    mma_tf32(acc[mf][nf], al[mf], bh[nf]);
                }
        }
    }
    // ---- epilogue (optional per-row dinv scale, optional fp16 out) ----
#pragma unroll
    for (int mf = 0; mf < 2; mf++) {
        int r = m0 + wm * 32 + mf * 16 + qt;
        float sc0 = 1.f, sc1 = 1.f;
        if (DG) {
            if (r < M) sc0 = rsqrtf((float)DG[r] + 1.f);
            if (r + 8 < M) sc1 = rsqrtf((float)DG[r + 8] + 1.f);
        }
#pragma unroll
        for (int nf = 0; nf < 8; nf++) {
            int cc = wn * 64 + nf * 8 + qr * 2;
            if (halfOut) {
                __half* CH = (__half*)Cv;
                if (r < M)
                    *(__half2*)(CH + (size_t)r * 128 + cc) =
                        __floats2half2_rn(sc0 * acc[mf][nf][0], sc0 * acc[mf][nf][1]);
                if (r + 8 < M)
                    *(__half2*)(CH + (size_t)(r + 8) * 128 + cc) =
                        __floats2half2_rn(sc1 * acc[mf][nf][2], sc1 * acc[mf][nf][3]);
            } else {
                float* C = (float*)Cv;
                if (r < M)
                    *(float2*)(C + (size_t)r * 128 + cc) =
                        make_float2(sc0 * acc[mf][nf][0], sc0 * acc[mf][nf][1]);
                if (r + 8 < M)
                    *(float2*)(C + (size_t)(r + 8) * 128 + cc) =
                        make_float2(sc1 * acc[mf][nf][2], sc1 * acc[mf][nf][3]);
            }
        }
    }
}

// ---------------- graph prep ----------------

__global__ void k_zero(const int* w) {
    int i = blockIdx.x * blockDim.x + threadIdx.x;
    if (i < 2 * Nn) g_degi[i] = 0;
    if (i < 1024) g_stats[i] = 0.f;
    if (blockIdx.x == 0) {
        __shared__ int anynz;
        if (threadIdx.x == 0) anynz = 0;
        __syncthreads();
        if (w[threadIdx.x * 2 + 1] != 0) atomicExch(&anynz, 1);
        __syncthreads();
        if (threadIdx.x == 0) g_is64 = (anynz == 0) ? 1 : 0;
    }
}

__global__ void k_cvt_deg(const void* __restrict__ beam, const void* __restrict__ col) {
    int t = blockIdx.x * blockDim.x + threadIdx.x;
    if (t >= 2 * Ee) return;
    int rel = (t >= Ee) ? 1 : 0;
    int e = t - rel * Ee;
    const void* ei = rel ? col : beam;
    int is64 = g_is64;
    int s = (int)ld_idx(ei, e, is64);
    int d = (int)ld_idx(ei, (long long)Ee + e, is64);
    g_eis[rel * Ee + e] = s;
    g_eid[rel * Ee + e] = d;
    atomicAdd(&g_degi[rel * Nn + d], 1);
}

// exclusive scan: 1024 threads x 49 serial nodes, one block-wide scan
#define SCH 49
__global__ void __launch_bounds__(1024) k_scan() {
    __shared__ int sh[1024];
    int tid = threadIdx.x;
    for (int rel = 0; rel < 2; rel++) {
        const int* deg = g_degi + rel * Nn;
        int* off = g_off + rel * (Nn + 1);
        int* cur = g_cursor + rel * Nn;
        int start = tid * SCH;
        int s = 0;
        int dl[SCH];
#pragma unroll
        for (int i = 0; i < SCH; i++) {
            int idx = start + i;
            dl[i] = (idx < Nn) ? deg[idx] : 0;
            s += dl[i];
        }
        sh[tid] = s;
        __syncthreads();
#pragma unroll
        for (int o = 1; o < 1024; o <<= 1) {
            int t = (tid >= o) ? sh[tid - o] : 0;
            __syncthreads();
            sh[tid] += t;
            __syncthreads();
        }
        int run = sh[tid] - s;   // exclusive prefix
#pragma unroll
        for (int i = 0; i < SCH; i++) {
            int idx = start + i;
            if (idx < Nn) {
                off[idx] = run;
                cur[idx] = run;
                run += dl[i];
            }
        }
        if (tid == 1023) off[Nn] = run;
        __syncthreads();
    }
}

__global__ void k_fill() {
    int t = blockIdx.x * blockDim.x + threadIdx.x;
    if (t >= 2 * Ee) return;
    int rel = (t >= Ee) ? 1 : 0;
    int e = t - rel * Ee;
    int d = g_eid[rel * Ee + e];
    int pos = atomicAdd(&g_cursor[rel * Nn + d], 1);
    g_csr[rel * Ee + pos] = g_eis[rel * Ee + e];
}

// ---------------- node encoder (smem-staged x) ----------------
__global__ void __launch_bounds__(128) k_encoder(const float* __restrict__ x,
                                                 const float* __restrict__ W,
                                                 const float* __restrict__ b) {
    __shared__ float sx[384];
    int c = threadIdx.x;
    int n0 = blockIdx.x * 128;
    float w0 = W[c], w1 = W[Hh + c], w2 = W[2 * Hh + c], bb = b[c];
#pragma unroll
    for (int i = c; i < 384; i += 128) {
        int gidx = n0 * 3 + i;
        sx[i] = (gidx < Nn * 3) ? x[gidx] : 0.f;
    }
    __syncthreads();
    int lim = Nn - n0; if (lim > 128) lim = 128;
    float s = 0.f, s2 = 0.f;
    for (int j = 0; j < lim; j++) {
        float v = fmaxf(fmaf(sx[3 * j + 2], w2, fmaf(sx[3 * j + 1], w1, fmaf(sx[3 * j], w0, bb))), 0.f);
        g_h[(size_t)(n0 + j) * 128 + c] = v;
        s += v; s2 += v * v;
    }
    atomicAdd(&g_stats[c], s);
    atomicAdd(&g_stats[Hh + c], s2);
}

// ---------------- fused GCN aggregation (CSR gather, 4x unrolled) ----------------
__global__ void k_agg(const float* __restrict__ bias_b, const float* __restrict__ bias_c,
                      int dorelu) {
    int gt = blockIdx.x * blockDim.x + threadIdx.x;
    int d = gt >> 5;
    if (d >= Nn) return;
    int l4 = (gt & 31) * 4;

    float4 o = make_float4(0.f, 0.f, 0.f, 0.f);
#pragma unroll
    for (int rel = 0; rel < 2; rel++) {
        const float* xs = g_xw + rel * NH;
        const int* csr = g_csr + rel * Ee;
        float4 acc = *(const float4*)(xs + (size_t)d * 128 + l4);
        int e = g_off[rel * (Nn + 1) + d];
        int end = g_off[rel * (Nn + 1) + d + 1];
        for (; e + 4 <= end; e += 4) {
            int s0 = csr[e], s1 = csr[e + 1], s2 = csr[e + 2], s3 = csr[e + 3];
            float4 v0 = *(const float4*)(xs + (size_t)s0 * 128 + l4);
            float4 v1 = *(const float4*)(xs + (size_t)s1 * 128 + l4);
            float4 v2 = *(const float4*)(xs + (size_t)s2 * 128 + l4);
            float4 v3 = *(const float4*)(xs + (size_t)s3 * 128 + l4);
            acc.x += v0.x + v1.x + v2.x + v3.x;
            acc.y += v0.y + v1.y + v2.y + v3.y;
            acc.z += v0.z + v1.z + v2.z + v3.z;
            acc.w += v0.w + v1.w + v2.w + v3.w;
        }
        for (; e < end; e++) {
            int s = csr[e];
            float4 v = *(const float4*)(xs + (size_t)s * 128 + l4);
            acc.x += v.x; acc.y += v.y; acc.z += v.z; acc.w += v.w;
        }
        float dv = rsqrtf((float)g_degi[rel * Nn + d] + 1.f);
        o.x = fmaf(dv, acc.x, o.x);
        o.y = fmaf(dv, acc.y, o.y);
        o.z = fmaf(dv, acc.z, o.z);
        o.w = fmaf(dv, acc.w, o.w);
    }
    float4 bb = *(const float4*)(bias_b + l4);
    float4 bc = *(const float4*)(bias_c + l4);
    o.x += bb.x + bc.x; o.y += bb.y + bc.y;
    o.z += bb.z + bc.z; o.w += bb.w + bc.w;
    if (dorelu) {
        o.x = fmaxf(o.x, 0.f); o.y = fmaxf(o.y, 0.f);
        o.z = fmaxf(o.z, 0.f); o.w = fmaxf(o.w, 0.f);
    }
    *(float4*)(g_h + (size_t)d * 128 + l4) = o;
}

// ---------------- edge predictors (fp16 P/Q, 2 edges per warp iter) ----------------

__device__ __forceinline__ float4 ld_pq4(const __half* base, int row, int l4) {
    const __half2* p2 = (const __half2*)(base + (size_t)row * 128 + l4);
    float2 a = __half22float2(p2[0]);
    float2 b = __half22float2(p2[1]);
    return make_float4(a.x, a.y, b.x, b.y);
}

__global__ void k_edge_stats(const __half* __restrict__ Pb, const __half* __restrict__ Qb,
                             const float* __restrict__ bb,
                             const __half* __restrict__ Pc, const __half* __restrict__ Qc,
                             const float* __restrict__ bc) {
    int rel = blockIdx.y;
    const __half* P = rel ? Pc : Pb;
    const __half* Q = rel ? Qc : Qb;
    const float* bias = rel ? bc : bb;
    const int* es = g_eis + rel * Ee;
    const int* ed = g_eid + rel * Ee;
    float* sum = g_stats + 256 + rel * 256;
    float* sq = sum + 128;

    int lane = threadIdx.x & 31;
    int warp = (blockIdx.x * blockDim.x + threadIdx.x) >> 5;
    int nw = (gridDim.x * blockDim.x) >> 5;
    int l4 = lane * 4;
    float4 b = ((const float4*)bias)[lane];
    float4 s = make_float4(0.f, 0.f, 0.f, 0.f);
    float4 s2 = make_float4(0.f, 0.f, 0.f, 0.f);
    // Ee is even: e+1 < Ee always holds inside the loop
    for (int e = warp * 2; e < Ee; e += nw * 2) {
        int si0 = es[e], di0 = ed[e];
        int si1 = es[e + 1], di1 = ed[e + 1];
        float4 p0 = ld_pq4(P, si0, l4);
        float4 q0 = ld_pq4(Q, di0, l4);
        float4 p1 = ld_pq4(P, si1, l4);
        float4 q1 = ld_pq4(Q, di1, l4);
        float4 z0, z1;
        z0.x = fmaxf(p0.x + q0.x + b.x, 0.f);
        z0.y = fmaxf(p0.y + q0.y + b.y, 0.f);
        z0.z = fmaxf(p0.z + q0.z + b.z, 0.f);
        z0.w = fmaxf(p0.w + q0.w + b.w, 0.f);
        z1.x = fmaxf(p1.x + q1.x + b.x, 0.f);
        z1.y = fmaxf(p1.y + q1.y + b.y, 0.f);
        z1.z = fmaxf(p1.z + q1.z + b.z, 0.f);
        z1.w = fmaxf(p1.w + q1.w + b.w, 0.f);
        s.x += z0.x + z1.x; s.y += z0.y + z1.y;
        s.z += z0.z + z1.z; s.w += z0.w + z1.w;
        s2.x = fmaf(z0.x, z0.x, fmaf(z1.x, z1.x, s2.x));
        s2.y = fmaf(z0.y, z0.y, fmaf(z1.y, z1.y, s2.y));
        s2.z = fmaf(z0.z, z0.z, fmaf(z1.z, z1.z, s2.z));
        s2.w = fmaf(z0.w, z0.w, fmaf(z1.w, z1.w, s2.w));
    }
    int c = lane * 4;
    atomicAdd(&sum[c + 0], s.x); atomicAdd(&sum[c + 1], s.y);
    atomicAdd(&sum[c + 2], s.z); atomicAdd(&sum[c + 3], s.w);
    atomicAdd(&sq[c + 0], s2.x); atomicAdd(&sq[c + 1], s2.y);
    atomicAdd(&sq[c + 2], s2.z); atomicAdd(&sq[c + 3], s2.w);
}

__global__ void k_bn_pred(const float* gb, const float* beb, const float* W2b, const float* b2b,
                          const float* gc, const float* bec, const float* W2c, const float* b2c) {
    __shared__ float r0s[Hh], r1s[Hh];
    int k = threadIdx.x;
    for (int rel = 0; rel < 2; rel++) {
        const float* g  = rel ? gc  : gb;
        const float* be = rel ? bec : beb;
        const float* W2 = rel ? W2c : W2b;
        const float* b2 = rel ? b2c : b2b;
        const float* sum = &g_stats[256 + rel * 256];
        const float* sq  = &g_stats[256 + rel * 256 + 128];
        float m = sum[k] * (1.0f / Ee);
        float v = sq[k] * (1.0f / Ee) - m * m;
        float a = g[k] * rsqrtf(v + EPSf);
        float cc = be[k] - a * m;
        float w0 = W2[k * 2], w1 = W2[k * 2 + 1];
        g_wp[rel][k * 2] = a * w0;
        g_wp[rel][k * 2 + 1] = a * w1;
        r0s[k] = cc * w0;
        r1s[k] = cc * w1;
        __syncthreads();
        for (int off = 64; off > 0; off >>= 1) {
            if (k < off) { r0s[k] += r0s[k + off]; r1s[k] += r1s[k + off]; }
            __syncthreads();
        }
        if (k == 0) {
            g_bp[rel][0] = r0s[0] + b2[0];
            g_bp[rel][1] = r1s[0] + b2[1];
        }
        __syncthreads();
    }
}

// 2 edges per warp (Ee even)
__global__ void k_pred(const __half* __restrict__ Pb, const __half* __restrict__ Qb,
                       const float* __restrict__ bb,
                       const __half* __restrict__ Pc, const __half* __restrict__ Qc,
                       const float* __restrict__ bc, float* __restrict__ outbase) {
    int rel = blockIdx.y;
    const __half* P = rel ? Pc : Pb;
    const __half* Q = rel ? Qc : Qb;
    const float* bias = rel ? bc : bb;
    const int* es = g_eis + rel * Ee;
    const int* ed = g_eid + rel * Ee;
    float* out = outbase + (size_t)rel * 2 * Ee;

    int gt = blockIdx.x * blockDim.x + threadIdx.x;
    int warp = gt >> 5;
    int lane = gt & 31;
    int e0 = warp * 2;
    if (e0 >= Ee) return;
    int l4 = lane * 4;
    float4 b = ((const float4*)bias)[lane];
    const float* W = g_wp[rel];
    float w00 = W[(l4 + 0) * 2], w01 = W[(l4 + 0) * 2 + 1];
    float w10 = W[(l4 + 1) * 2], w11 = W[(l4 + 1) * 2 + 1];
    float w20 = W[(l4 + 2) * 2], w21 = W[(l4 + 2) * 2 + 1];
    float w30 = W[(l4 + 3) * 2], w31 = W[(l4 + 3) * 2 + 1];
    int si0 = es[e0], di0 = ed[e0];
    int si1 = es[e0 + 1], di1 = ed[e0 + 1];
    float4 p0 = ld_pq4(P, si0, l4);
    float4 q0 = ld_pq4(Q, di0, l4);
    float4 p1 = ld_pq4(P, si1, l4);
    float4 q1 = ld_pq4(Q, di1, l4);
    float4 z0, z1;
    z0.x = fmaxf(p0.x + q0.x + b.x, 0.f);
    z0.y = fmaxf(p0.y + q0.y + b.y, 0.f);
    z0.z = fmaxf(p0.z + q0.z + b.z, 0.f);
    z0.w = fmaxf(p0.w + q0.w + b.w, 0.f);
    z1.x = fmaxf(p1.x + q1.x + b.x, 0.f);
    z1.y = fmaxf(p1.y + q1.y + b.y, 0.f);
    z1.z = fmaxf(p1.z + q1.z + b.z, 0.f);
    z1.w = fmaxf(p1.w + q1.w + b.w, 0.f);
    float s00 = z0.x * w00 + z0.y * w10 + z0.z * w20 + z0.w * w30;
    float s01 = z0.x * w01 + z0.y * w11 + z0.z * w21 + z0.w * w31;
    float s10 = z1.x * w00 + z1.y * w10 + z1.z * w20 + z1.w * w30;
    float s11 = z1.x * w01 + z1.y * w11 + z1.z * w21 + z1.w * w31;
#pragma unroll
    for (int off = 16; off > 0; off >>= 1) {
        s00 += __shfl_xor_sync(0xffffffffu, s00, off);
        s01 += __shfl_xor_sync(0xffffffffu, s01, off);
        s10 += __shfl_xor_sync(0xffffffffu, s10, off);
        s11 += __shfl_xor_sync(0xffffffffu, s11, off);
    }
    if (lane == 0) {
        float b0 = g_bp[rel][0], b1 = g_bp[rel][1];
        ((float2*)out)[e0] = make_float2(s00 + b0, s01 + b1);
        ((float2*)out)[e0 + 1] = make_float2(s10 + b0, s11 + b1);
    }
}

__global__ void k_etypes(float* __restrict__ out) {
    int i = blockIdx.x * blockDim.x + threadIdx.x;
    if (i < 2 * Ee) out[i] = (i < Ee) ? 0.f : 1.f;
}

// ---------------- host ----------------
extern "C" void kernel_launch(void* const* d_in, const int* in_sizes, int n_in,
                              void* d_out, int out_size) {
    (void)in_sizes; (void)n_in; (void)out_size;
    const float* x     = (const float*)d_in[0];
    const void*  beam  = d_in[1];
    const void*  col   = d_in[2];
    const float* W_enc = (const float*)d_in[3];
    const float* b_enc = (const float*)d_in[4];
    const float* g_enc = (const float*)d_in[5];
    const float* be_enc= (const float*)d_in[6];
    const float* W1b   = (const float*)d_in[7];
    const float* b1b   = (const float*)d_in[8];
    const float* W1c   = (const float*)d_in[9];
    const float* b1c   = (const float*)d_in[10];
    const float* W2b   = (const float*)d_in[11];
    const float* b2b   = (const float*)d_in[12];
    const float* W2c   = (const float*)d_in[13];
    const float* b2c   = (const float*)d_in[14];
    const float* Wbp1  = (const float*)d_in[15];
    const float* bbp1  = (const float*)d_in[16];
    const float* gbp   = (const float*)d_in[17];
    const float* bebp  = (const float*)d_in[18];
    const float* Wbp2  = (const float*)d_in[19];
    const float* bbp2  = (const float*)d_in[20];
    const float* Wcp1  = (const float*)d_in[21];
    const float* bcp1  = (const float*)d_in[22];
    const float* gcp   = (const float*)d_in[23];
    const float* becp  = (const float*)d_in[24];
    const float* Wcp2  = (const float*)d_in[25];
    const float* bcp2  = (const float*)d_in[26];
    float* out = (float*)d_out;

    float *p_h, *p_xw;
    __half* p_pq;
    int *p_deg;
    cudaGetSymbolAddress((void**)&p_h, g_h);
    cudaGetSymbolAddress((void**)&p_xw, g_xw);
    cudaGetSymbolAddress((void**)&p_pq, g_pqh);
    cudaGetSymbolAddress((void**)&p_deg, g_degi);

    cudaFuncSetAttribute(k_mma, cudaFuncAttributeMaxDynamicSharedMemorySize, SMEM_MM);

    const int GB = (Nn + 127) / 128;   // 391 M-tiles
    const int EV2 = (Ee / 2) * 32;     // 2 edges per warp
    const int NW = Nn * 32;

    k_zero<<<(2 * Nn + 255) / 256, 256>>>((const int*)beam);                 // 1
    k_cvt_deg<<<(2 * Ee + 255) / 256, 256>>>(beam, col);                     // 2
    k_encoder<<<GB, 128>>>(x, W_enc, b_enc);                                 // 3

    // GCN layer 1: xs_rel = dinv_rel * (bnaffine(h0) @ W1_rel)              // 4 <- profiled
    k_mma<<<dim3(GB, 2), 256, SMEM_MM>>>(p_h, W1b, W1c, W1b, W1b,
                                         p_xw, p_xw + NH, p_xw, p_xw,
                                         p_deg, p_deg + Nn,
                                         g_enc, be_enc, 0, Nn);
    k_scan<<<1, 1024>>>();                                                   // 5
    k_fill<<<(2 * Ee + 255) / 256, 256>>>();                                 // 6
    k_agg<<<(NW + 255) / 256, 256>>>(b1b, b1c, 1);                           // 7

    // GCN layer 2
    k_mma<<<dim3(GB, 2), 256, SMEM_MM>>>(p_h, W2b, W2c, W2b, W2b,            // 8
                                         p_xw, p_xw + NH, p_xw, p_xw,
                                         p_deg, p_deg + Nn,
                                         nullptr, nullptr, 0, Nn);
    k_agg<<<(NW + 255) / 256, 256>>>(b2b, b2c, 0);                           // 9

    // edge predictors: P/Q = h2 @ (top/bottom halves of Wbp1 / Wcp1), fp16 out
    k_mma<<<dim3(GB, 4), 256, SMEM_MM>>>(p_h, Wbp1, Wbp1 + Hh * Hh,          // 10
                                         Wcp1, Wcp1 + Hh * Hh,
                                         p_pq, p_pq + NH, p_pq + 2 * NH, p_pq + 3 * NH,
                                         nullptr, nullptr,
                                         nullptr, nullptr, 1, Nn);

    k_edge_stats<<<dim3(512, 2), 256>>>(p_pq, p_pq + NH, bbp1,               // 11
                                        p_pq + 2 * NH, p_pq + 3 * NH, bcp1);
    k_bn_pred<<<1, 128>>>(gbp, bebp, Wbp2, bbp2, gcp, becp, Wcp2, bcp2);     // 12
    k_pred<<<dim3((EV2 + 255) / 256, 2), 256>>>(p_pq, p_pq + NH, bbp1,       // 13
                                                p_pq + 2 * NH, p_pq + 3 * NH, bcp1, out);
    k_etypes<<<(2 * Ee + 255) / 256, 256>>>(out + 4 * Ee);                   // 14
}

// round 15
// speedup vs baseline: 1.1486x; 1.0377x over previous
#include <cuda_runtime.h>
#include <cuda_fp16.h>
#include <stdint.h>

#define Nn 50000
#define Ee 250000
#define Hh 128
#define NH (Nn*Hh)
#define EPSf 1e-5f

// ---------------- device scratch (static, no allocs) ----------------
__device__ float  g_h[NH];           // node features (h0 -> h1 -> h2)
__device__ float  g_xw[2*NH];        // xs per relation (dinv-scaled gemm out)
__device__ __half g_pqh[4*NH];       // Pb, Qb, Pc, Qc in fp16
__device__ int    g_degi[2*Nn];      // in-degree per relation
__device__ int    g_off[2*(Nn+1)];   // CSR offsets per relation
__device__ int    g_cursor[2*Nn];    // fill cursors
__device__ int    g_eis[2*Ee];       // int32 src per relation
__device__ int    g_eid[2*Ee];       // int32 dst per relation
__device__ int    g_csr[2*Ee];       // CSR src lists
__device__ float  g_stats[1024];     // enc sums [0:256), beam [256:512), col [512:768)
__device__ float  g_wp[2][Hh*2];     // folded BN*Wbp2 per relation
__device__ float  g_bp[2][2];        // folded bias per relation
__device__ int    g_is64;

// ---------------- helpers ----------------
__device__ __forceinline__ long long ld_idx(const void* p, long long i, int is64) {
    return is64 ? ((const long long*)p)[i] : (long long)((const int*)p)[i];
}

__device__ __forceinline__ uint32_t tf32_rna(float x) {
    uint32_t r;
    asm("cvt.rna.tf32.f32 %0, %1;" : "=r"(r) : "f"(x));
    return r;
}

__device__ __forceinline__ void mma_tf32(float* d, const uint32_t* a, const uint32_t* b) {
    asm volatile(
        "mma.sync.aligned.m16n8k8.row.col.f32.tf32.tf32.f32 "
        "{%0,%1,%2,%3}, {%4,%5,%6,%7}, {%8,%9}, {%0,%1,%2,%3};"
        : "+f"(d[0]), "+f"(d[1]), "+f"(d[2]), "+f"(d[3])
        : "r"(a[0]), "r"(a[1]), "r"(a[2]), "r"(a[3]), "r"(b[0]), "r"(b[1]));
}

// ---------------- mma.sync 3xTF32 GEMM (R12-proven: split at fill, LDS.32) ----------------
#define APAD 36
#define BPAD 136
#define AC_OFF (128*APAD*2 + 32*BPAD*2)
#define SMEM_MM ((AC_OFF + 256) * 4)

__global__ void __launch_bounds__(256, 2)
k_mma(const float* __restrict__ A,
      const float* __restrict__ W0, const float* __restrict__ W1,
      const float* __restrict__ W2, const float* __restrict__ W3,
      void* __restrict__ C0, void* __restrict__ C1,
      void* __restrict__ C2, void* __restrict__ C3,
      const int* __restrict__ D0, const int* __restrict__ D1,
      const float* __restrict__ gEnc, const float* __restrict__ beEnc,
      int halfOut, int M) {
    extern __shared__ uint32_t sm[];
    uint32_t* Ahi = sm;                       // [128][APAD]
    uint32_t* Alo = Ahi + 128 * APAD;
    uint32_t* Bhi = Alo + 128 * APAD;         // [32][BPAD]
    uint32_t* Blo = Bhi + 32 * BPAD;
    float* acs = (float*)(sm + AC_OFF);       // [256] BN affine a|c

    int tid = threadIdx.x;
    int lane = tid & 31, wid = tid >> 5;
    int wm = wid >> 1, wn = wid & 1;          // warp grid 4x2
    int m0 = blockIdx.x * 128;
    int qt = lane >> 2;                       // 0..7
    int qr = lane & 3;                        // 0..3

    const float* W = (blockIdx.y == 0) ? W0 : (blockIdx.y == 1) ? W1 : (blockIdx.y == 2) ? W2 : W3;
    void* Cv = (blockIdx.y == 0) ? C0 : (blockIdx.y == 1) ? C1 : (blockIdx.y == 2) ? C2 : C3;
    const int* DG = (blockIdx.y == 0) ? D0 : (blockIdx.y == 1) ? D1 : nullptr;

    if (gEnc && tid < 128) {
        float m = g_stats[tid] * (1.0f / Nn);
        float v = g_stats[128 + tid] * (1.0f / Nn) - m * m;
        float a = gEnc[tid] * rsqrtf(v + EPSf);
        acs[tid] = a;
        acs[128 + tid] = beEnc[tid] - a * m;
    }
    __syncthreads();

    float acc[2][8][4];
#pragma unroll
    for (int i = 0; i < 2; i++)
#pragma unroll
        for (int j = 0; j < 8; j++)
#pragma unroll
            for (int q = 0; q < 4; q++) acc[i][j][q] = 0.f;

    for (int ch = 0; ch < 4; ch++) {
        int k0 = ch * 32;
        if (ch > 0) __syncthreads();
        // ---- fill A chunk [128 rows x 32 k] hi/lo (optional BN affine) ----
#pragma unroll
        for (int rep = 0; rep < 4; rep++) {
            int i4 = tid + rep * 256;         // 0..1023 float4s
            int r = i4 >> 3;                  // row 0..127
            int c = (i4 & 7) * 4;             // k 0..28
            float4 v = make_float4(0.f, 0.f, 0.f, 0.f);
            if (m0 + r < M) v = *(const float4*)(A + (size_t)(m0 + r) * 128 + k0 + c);
            if (gEnc) {
                float4 a4 = *(const float4*)(acs + k0 + c);
                float4 c4 = *(const float4*)(acs + 128 + k0 + c);
                v.x = fmaf(a4.x, v.x, c4.x);
                v.y = fmaf(a4.y, v.y, c4.y);
                v.z = fmaf(a4.z, v.z, c4.z);
                v.w = fmaf(a4.w, v.w, c4.w);
            }
            uint4 h, l;
            h.x = tf32_rna(v.x); l.x = tf32_rna(v.x - __uint_as_float(h.x));
            h.y = tf32_rna(v.y); l.y = tf32_rna(v.y - __uint_as_float(h.y));
            h.z = tf32_rna(v.z); l.z = tf32_rna(v.z - __uint_as_float(h.z));
            h.w = tf32_rna(v.w); l.w = tf32_rna(v.w - __uint_as_float(h.w));
            *(uint4*)(Ahi + r * APAD + c) = h;
            *(uint4*)(Alo + r * APAD + c) = l;
        }
        // ---- fill B chunk: Bs[k][n] = W[(k0+k)*128 + n] ----
#pragma unroll
        for (int rep = 0; rep < 4; rep++) {
            int i4 = tid + rep * 256;
            int kk = i4 >> 5;                 // 0..31
            int n = (i4 & 31) * 4;            // 0..124
            float4 v = *(const float4*)(W + (size_t)(k0 + kk) * 128 + n);
            uint4 h, l;
            h.x = tf32_rna(v.x); l.x = tf32_rna(v.x - __uint_as_float(h.x));
            h.y = tf32_rna(v.y); l.y = tf32_rna(v.y - __uint_as_float(h.y));
            h.z = tf32_rna(v.z); l.z = tf32_rna(v.z - __uint_as_float(h.z));
            h.w = tf32_rna(v.w); l.w = tf32_rna(v.w - __uint_as_float(h.w));
            *(uint4*)(Bhi + kk * BPAD + n) = h;
            *(uint4*)(Blo + kk * BPAD + n) = l;
        }
        __syncthreads();
        // ---- compute 4 k-steps of 8 ----
#pragma unroll
        for (int s = 0; s < 4; s++) {
            int k = s * 8;
            uint32_t ah[2][4], al[2][4];
#pragma unroll
            for (int mf = 0; mf < 2; mf++) {
                int r0 = wm * 32 + mf * 16 + qt;
                int kc = k + qr;
                ah[mf][0] = Ahi[r0 * APAD + kc];
                ah[mf][1] = Ahi[(r0 + 8) * APAD + kc];
                ah[mf][2] = Ahi[r0 * APAD + kc + 4];
                ah[mf][3] = Ahi[(r0 + 8) * APAD + kc + 4];
                al[mf][0] = Alo[r0 * APAD + kc];
                al[mf][1] = Alo[(r0 + 8) * APAD + kc];
                al[mf][2] = Alo[r0 * APAD + kc + 4];
                al[mf][3] = Alo[(r0 + 8) * APAD + kc + 4];
            }
            uint32_t bh[8][2], bl[8][2];
#pragma unroll
            for (int nf = 0; nf < 8; nf++) {
                int cn = wn * 64 + nf * 8 + qt;
                int kr = k + qr;
                bh[nf][0] = Bhi[kr * BPAD + cn];
                bh[nf][1] = Bhi[(kr + 4) * BPAD + cn];
                bl[nf][0] = Blo[kr * BPAD + cn];
                bl[nf][1] = Blo[(kr + 4) * BPAD + cn];
            }
#pragma unroll
            for (int mf = 0; mf < 2; mf++)
#pragma unroll
                for (int nf = 0; nf < 8; nf++) {
                    mma_tf32(acc[mf][nf], ah[mf], bh[nf]);
                    mma_tf32(acc[mf][nf], ah[mf], bl[nf]);
                    mma_tf32(acc[mf][nf], al[mf], bh[nf]);
                }
        }
    }
    // ---- epilogue (optional per-row dinv scale, optional fp16 out) ----
#pragma unroll
    for (int mf = 0; mf < 2; mf++) {
        int r = m0 + wm * 32 + mf * 16 + qt;
        float sc0 = 1.f, sc1 = 1.f;
        if (DG) {
            if (r < M) sc0 = rsqrtf((float)DG[r] + 1.f);
            if (r + 8 < M) sc1 = rsqrtf((float)DG[r + 8] + 1.f);
        }
#pragma unroll
        for (int nf = 0; nf < 8; nf++) {
            int cc = wn * 64 + nf * 8 + qr * 2;
            if (halfOut) {
                __half* CH = (__half*)Cv;
                if (r < M)
                    *(__half2*)(CH + (size_t)r * 128 + cc) =
                        __floats2half2_rn(sc0 * acc[mf][nf][0], sc0 * acc[mf][nf][1]);
                if (r + 8 < M)
                    *(__half2*)(CH + (size_t)(r + 8) * 128 + cc) =
                        __floats2half2_rn(sc1 * acc[mf][nf][2], sc1 * acc[mf][nf][3]);
            } else {
                float* C = (float*)Cv;
                if (r < M)
                    *(float2*)(C + (size_t)r * 128 + cc) =
                        make_float2(sc0 * acc[mf][nf][0], sc0 * acc[mf][nf][1]);
                if (r + 8 < M)
                    *(float2*)(C + (size_t)(r + 8) * 128 + cc) =
                        make_float2(sc1 * acc[mf][nf][2], sc1 * acc[mf][nf][3]);
            }
        }
    }
}

// ---------------- graph prep ----------------

// zero buffers + detect int64 + write etypes output (independent region)
__global__ void k_zero(const int* w, float* __restrict__ et) {
    int i = blockIdx.x * blockDim.x + threadIdx.x;
    if (i < 2 * Nn) g_degi[i] = 0;
    if (i < 1024) g_stats[i] = 0.f;
    if (i < 2 * Ee) et[i] = (i < Ee) ? 0.f : 1.f;
    if (blockIdx.x == 0) {
        __shared__ int anynz;
        if (threadIdx.x == 0) anynz = 0;
        __syncthreads();
        if (w[threadIdx.x * 2 + 1] != 0) atomicExch(&anynz, 1);
        __syncthreads();
        if (threadIdx.x == 0) g_is64 = (anynz == 0) ? 1 : 0;
    }
}

__global__ void k_cvt_deg(const void* __restrict__ beam, const void* __restrict__ col) {
    int t = blockIdx.x * blockDim.x + threadIdx.x;
    if (t >= 2 * Ee) return;
    int rel = (t >= Ee) ? 1 : 0;
    int e = t - rel * Ee;
    const void* ei = rel ? col : beam;
    int is64 = g_is64;
    int s = (int)ld_idx(ei, e, is64);
    int d = (int)ld_idx(ei, (long long)Ee + e, is64);
    g_eis[rel * Ee + e] = s;
    g_eid[rel * Ee + e] = d;
    atomicAdd(&g_degi[rel * Nn + d], 1);
}

// exclusive scan: 1024 threads x 49 serial nodes, one block-wide scan
#define SCH 49
__global__ void __launch_bounds__(1024) k_scan() {
    __shared__ int sh[1024];
    int tid = threadIdx.x;
    for (int rel = 0; rel < 2; rel++) {
        const int* deg = g_degi + rel * Nn;
        int* off = g_off + rel * (Nn + 1);
        int* cur = g_cursor + rel * Nn;
        int start = tid * SCH;
        int s = 0;
        int dl[SCH];
#pragma unroll
        for (int i = 0; i < SCH; i++) {
            int idx = start + i;
            dl[i] = (idx < Nn) ? deg[idx] : 0;
            s += dl[i];
        }
        sh[tid] = s;
        __syncthreads();
#pragma unroll
        for (int o = 1; o < 1024; o <<= 1) {
            int t = (tid >= o) ? sh[tid - o] : 0;
            __syncthreads();
            sh[tid] += t;
            __syncthreads();
        }
        int run = sh[tid] - s;   // exclusive prefix
#pragma unroll
        for (int i = 0; i < SCH; i++) {
            int idx = start + i;
            if (idx < Nn) {
                off[idx] = run;
                cur[idx] = run;
                run += dl[i];
            }
        }
        if (tid == 1023) off[Nn] = run;
        __syncthreads();
    }
}

__global__ void k_fill() {
    int t = blockIdx.x * blockDim.x + threadIdx.x;
    if (t >= 2 * Ee) return;
    int rel = (t >= Ee) ? 1 : 0;
    int e = t - rel * Ee;
    int d = g_eid[rel * Ee + e];
    int pos = atomicAdd(&g_cursor[rel * Nn + d], 1);
    g_csr[rel * Ee + pos] = g_eis[rel * Ee + e];
}

// ---------------- node encoder (smem-staged x) ----------------
__global__ void __launch_bounds__(128) k_encoder(const float* __restrict__ x,
                                                 const float* __restrict__ W,
                                                 const float* __restrict__ b) {
    __shared__ float sx[384];
    int c = threadIdx.x;
    int n0 = blockIdx.x * 128;
    float w0 = W[c], w1 = W[Hh + c], w2 = W[2 * Hh + c], bb = b[c];
#pragma unroll
    for (int i = c; i < 384; i += 128) {
        int gidx = n0 * 3 + i;
        sx[i] = (gidx < Nn * 3) ? x[gidx] : 0.f;
    }
    __syncthreads();
    int lim = Nn - n0; if (lim > 128) lim = 128;
    float s = 0.f, s2 = 0.f;
    for (int j = 0; j < lim; j++) {
        float v = fmaxf(fmaf(sx[3 * j + 2], w2, fmaf(sx[3 * j + 1], w1, fmaf(sx[3 * j], w0, bb))), 0.f);
        g_h[(size_t)(n0 + j) * 128 + c] = v;
        s += v; s2 += v * v;
    }
    atomicAdd(&g_stats[c], s);
    atomicAdd(&g_stats[Hh + c], s2);
}

// ---------------- fused GCN aggregation (CSR gather, 4x unrolled) ----------------
__global__ void k_agg(const float* __restrict__ bias_b, const float* __restrict__ bias_c,
                      int dorelu) {
    int gt = blockIdx.x * blockDim.x + threadIdx.x;
    int d = gt >> 5;
    if (d >= Nn) return;
    int l4 = (gt & 31) * 4;

    float4 o = make_float4(0.f, 0.f, 0.f, 0.f);
#pragma unroll
    for (int rel = 0; rel < 2; rel++) {
        const float* xs = g_xw + rel * NH;
        const int* csr = g_csr + rel * Ee;
        float4 acc = *(const float4*)(xs + (size_t)d * 128 + l4);
        int e = g_off[rel * (Nn + 1) + d];
        int end = g_off[rel * (Nn + 1) + d + 1];
        for (; e + 4 <= end; e += 4) {
            int s0 = csr[e], s1 = csr[e + 1], s2 = csr[e + 2], s3 = csr[e + 3];
            float4 v0 = *(const float4*)(xs + (size_t)s0 * 128 + l4);
            float4 v1 = *(const float4*)(xs + (size_t)s1 * 128 + l4);
            float4 v2 = *(const float4*)(xs + (size_t)s2 * 128 + l4);
            float4 v3 = *(const float4*)(xs + (size_t)s3 * 128 + l4);
            acc.x += v0.x + v1.x + v2.x + v3.x;
            acc.y += v0.y + v1.y + v2.y + v3.y;
            acc.z += v0.z + v1.z + v2.z + v3.z;
            acc.w += v0.w + v1.w + v2.w + v3.w;
        }
        for (; e < end; e++) {
            int s = csr[e];
            float4 v = *(const float4*)(xs + (size_t)s * 128 + l4);
            acc.x += v.x; acc.y += v.y; acc.z += v.z; acc.w += v.w;
        }
        float dv = rsqrtf((float)g_degi[rel * Nn + d] + 1.f);
        o.x = fmaf(dv, acc.x, o.x);
        o.y = fmaf(dv, acc.y, o.y);
        o.z = fmaf(dv, acc.z, o.z);
        o.w = fmaf(dv, acc.w, o.w);
    }
    float4 bb = *(const float4*)(bias_b + l4);
    float4 bc = *(const float4*)(bias_c + l4);
    o.x += bb.x + bc.x; o.y += bb.y + bc.y;
    o.z += bb.z + bc.z; o.w += bb.w + bc.w;
    if (dorelu) {
        o.x = fmaxf(o.x, 0.f); o.y = fmaxf(o.y, 0.f);
        o.z = fmaxf(o.z, 0.f); o.w = fmaxf(o.w, 0.f);
    }
    *(float4*)(g_h + (size_t)d * 128 + l4) = o;
}

// ---------------- edge predictors (fp16 P/Q, 4 edges per warp iter) ----------------

__device__ __forceinline__ float4 ld_pq4(const __half* base, int row, int l4) {
    const __half2* p2 = (const __half2*)(base + (size_t)row * 128 + l4);
    float2 a = __half22float2(p2[0]);
    float2 b = __half22float2(p2[1]);
    return make_float4(a.x, a.y, b.x, b.y);
}

__device__ __forceinline__ float4 relu_add(float4 p, float4 q, float4 b) {
    float4 z;
    z.x = fmaxf(p.x + q.x + b.x, 0.f);
    z.y = fmaxf(p.y + q.y + b.y, 0.f);
    z.z = fmaxf(p.z + q.z + b.z, 0.f);
    z.w = fmaxf(p.w + q.w + b.w, 0.f);
    return z;
}

__global__ void k_edge_stats(const __half* __restrict__ Pb, const __half* __restrict__ Qb,
                             const float* __restrict__ bb,
                             const __half* __restrict__ Pc, const __half* __restrict__ Qc,
                             const float* __restrict__ bc) {
    int rel = blockIdx.y;
    const __half* P = rel ? Pc : Pb;
    const __half* Q = rel ? Qc : Qb;
    const float* bias = rel ? bc : bb;
    const int* es = g_eis + rel * Ee;
    const int* ed = g_eid + rel * Ee;
    float* sum = g_stats + 256 + rel * 256;
    float* sq = sum + 128;

    int lane = threadIdx.x & 31;
    int warp = (blockIdx.x * blockDim.x + threadIdx.x) >> 5;
    int nw = (gridDim.x * blockDim.x) >> 5;
    int l4 = lane * 4;
    float4 b = ((const float4*)bias)[lane];
    float4 s = make_float4(0.f, 0.f, 0.f, 0.f);
    float4 s2 = make_float4(0.f, 0.f, 0.f, 0.f);
    // Ee % 4 == 0: e..e+3 in range inside loop
    for (int e = warp * 4; e < Ee; e += nw * 4) {
        int si0 = es[e], di0 = ed[e];
        int si1 = es[e + 1], di1 = ed[e + 1];
        int si2 = es[e + 2], di2 = ed[e + 2];
        int si3 = es[e + 3], di3 = ed[e + 3];
        float4 p0 = ld_pq4(P, si0, l4), q0 = ld_pq4(Q, di0, l4);
        float4 p1 = ld_pq4(P, si1, l4), q1 = ld_pq4(Q, di1, l4);
        float4 p2 = ld_pq4(P, si2, l4), q2 = ld_pq4(Q, di2, l4);
        float4 p3 = ld_pq4(P, si3, l4), q3 = ld_pq4(Q, di3, l4);
        float4 z0 = relu_add(p0, q0, b);
        float4 z1 = relu_add(p1, q1, b);
        float4 z2 = relu_add(p2, q2, b);
        float4 z3 = relu_add(p3, q3, b);
        s.x += (z0.x + z1.x) + (z2.x + z3.x);
        s.y += (z0.y + z1.y) + (z2.y + z3.y);
        s.z += (z0.z + z1.z) + (z2.z + z3.z);
        s.w += (z0.w + z1.w) + (z2.w + z3.w);
        s2.x = fmaf(z0.x, z0.x, fmaf(z1.x, z1.x, fmaf(z2.x, z2.x, fmaf(z3.x, z3.x, s2.x))));
        s2.y = fmaf(z0.y, z0.y, fmaf(z1.y, z1.y, fmaf(z2.y, z2.y, fmaf(z3.y, z3.y, s2.y))));
        s2.z = fmaf(z0.z, z0.z, fmaf(z1.z, z1.z, fmaf(z2.z, z2.z, fmaf(z3.z, z3.z, s2.z))));
        s2.w = fmaf(z0.w, z0.w, fmaf(z1.w, z1.w, fmaf(z2.w, z2.w, fmaf(z3.w, z3.w, s2.w))));
    }
    int c = lane * 4;
    atomicAdd(&sum[c + 0], s.x); atomicAdd(&sum[c + 1], s.y);
    atomicAdd(&sum[c + 2], s.z); atomicAdd(&sum[c + 3], s.w);
    atomicAdd(&sq[c + 0], s2.x); atomicAdd(&sq[c + 1], s2.y);
    atomicAdd(&sq[c + 2], s2.z); atomicAdd(&sq[c + 3], s2.w);
}

__global__ void k_bn_pred(const float* gb, const float* beb, const float* W2b, const float* b2b,
                          const float* gc, const float* bec, const float* W2c, const float* b2c) {
    __shared__ float r0s[Hh], r1s[Hh];
    int k = threadIdx.x;
    for (int rel = 0; rel < 2; rel++) {
        const float* g  = rel ? gc  : gb;
        const float* be = rel ? bec : beb;
        const float* W2 = rel ? W2c : W2b;
        const float* b2 = rel ? b2c : b2b;
        const float* sum = &g_stats[256 + rel * 256];
        const float* sq  = &g_stats[256 + rel * 256 + 128];
        float m = sum[k] * (1.0f / Ee);
        float v = sq[k] * (1.0f / Ee) - m * m;
        float a = g[k] * rsqrtf(v + EPSf);
        float cc = be[k] - a * m;
        float w0 = W2[k * 2], w1 = W2[k * 2 + 1];
        g_wp[rel][k * 2] = a * w0;
        g_wp[rel][k * 2 + 1] = a * w1;
        r0s[k] = cc * w0;
        r1s[k] = cc * w1;
        __syncthreads();
        for (int off = 64; off > 0; off >>= 1) {
            if (k < off) { r0s[k] += r0s[k + off]; r1s[k] += r1s[k + off]; }
            __syncthreads();
        }
        if (k == 0) {
            g_bp[rel][0] = r0s[0] + b2[0];
            g_bp[rel][1] = r1s[0] + b2[1];
        }
        __syncthreads();
    }
}

// 4 edges per warp (Ee % 4 == 0)
__global__ void k_pred(const __half* __restrict__ Pb, const __half* __restrict__ Qb,
                       const float* __restrict__ bb,
                       const __half* __restrict__ Pc, const __half* __restrict__ Qc,
                       const float* __restrict__ bc, float* __restrict__ outbase) {
    int rel = blockIdx.y;
    const __half* P = rel ? Pc : Pb;
    const __half* Q = rel ? Qc : Qb;
    const float* bias = rel ? bc : bb;
    const int* es = g_eis + rel * Ee;
    const int* ed = g_eid + rel * Ee;
    float* out = outbase + (size_t)rel * 2 * Ee;

    int gt = blockIdx.x * blockDim.x + threadIdx.x;
    int warp = gt >> 5;
    int lane = gt & 31;
    int e0 = warp * 4;
    if (e0 >= Ee) return;
    int l4 = lane * 4;
    float4 b = ((const float4*)bias)[lane];
    const float* W = g_wp[rel];
    float w00 = W[(l4 + 0) * 2], w01 = W[(l4 + 0) * 2 + 1];
    float w10 = W[(l4 + 1) * 2], w11 = W[(l4 + 1) * 2 + 1];
    float w20 = W[(l4 + 2) * 2], w21 = W[(l4 + 2) * 2 + 1];
    float w30 = W[(l4 + 3) * 2], w31 = W[(l4 + 3) * 2 + 1];
    int si0 = es[e0], di0 = ed[e0];
    int si1 = es[e0 + 1], di1 = ed[e0 + 1];
    int si2 = es[e0 + 2], di2 = ed[e0 + 2];
    int si3 = es[e0 + 3], di3 = ed[e0 + 3];
    float4 p0 = ld_pq4(P, si0, l4), q0 = ld_pq4(Q, di0, l4);
    float4 p1 = ld_pq4(P, si1, l4), q1 = ld_pq4(Q, di1, l4);
    float4 p2 = ld_pq4(P, si2, l4), q2 = ld_pq4(Q, di2, l4);
    float4 p3 = ld_pq4(P, si3, l4), q3 = ld_pq4(Q, di3, l4);
    float4 z0 = relu_add(p0, q0, b);
    float4 z1 = relu_add(p1, q1, b);
    float4 z2 = relu_add(p2, q2, b);
    float4 z3 = relu_add(p3, q3, b);
    float s00 = z0.x * w00 + z0.y * w10 + z0.z * w20 + z0.w * w30;
    float s01 = z0.x * w01 + z0.y * w11 + z0.z * w21 + z0.w * w31;
    float s10 = z1.x * w00 + z1.y * w10 + z1.z * w20 + z1.w * w30;
    float s11 = z1.x * w01 + z1.y * w11 + z1.z * w21 + z1.w * w31;
    float s20 = z2.x * w00 + z2.y * w10 + z2.z * w20 + z2.w * w30;
    float s21 = z2.x * w01 + z2.y * w11 + z2.z * w21 + z2.w * w31;
    float s30 = z3.x * w00 + z3.y * w10 + z3.z * w20 + z3.w * w30;
    float s31 = z3.x * w01 + z3.y * w11 + z3.z * w21 + z3.w * w31;
#pragma unroll
    for (int off = 16; off > 0; off >>= 1) {
        s00 += __shfl_xor_sync(0xffffffffu, s00, off);
        s01 += __shfl_xor_sync(0xffffffffu, s01, off);
        s10 += __shfl_xor_sync(0xffffffffu, s10, off);
        s11 += __shfl_xor_sync(0xffffffffu, s11, off);
        s20 += __shfl_xor_sync(0xffffffffu, s20, off);
        s21 += __shfl_xor_sync(0xffffffffu, s21, off);
        s30 += __shfl_xor_sync(0xffffffffu, s30, off);
        s31 += __shfl_xor_sync(0xffffffffu, s31, off);
    }
    if (lane == 0) {
        float b0 = g_bp[rel][0], b1 = g_bp[rel][1];
        ((float2*)out)[e0] = make_float2(s00 + b0, s01 + b1);
        ((float2*)out)[e0 + 1] = make_float2(s10 + b0, s11 + b1);
        ((float2*)out)[e0 + 2] = make_float2(s20 + b0, s21 + b1);
        ((float2*)out)[e0 + 3] = make_float2(s30 + b0, s31 + b1);
    }
}

// ---------------- host ----------------
extern "C" void kernel_launch(void* const* d_in, const int* in_sizes, int n_in,
                              void* d_out, int out_size) {
    (void)in_sizes; (void)n_in; (void)out_size;
    const float* x     = (const float*)d_in[0];
    const void*  beam  = d_in[1];
    const void*  col   = d_in[2];
    const float* W_enc = (const float*)d_in[3];
    const float* b_enc = (const float*)d_in[4];
    const float* g_enc = (const float*)d_in[5];
    const float* be_enc= (const float*)d_in[6];
    const float* W1b   = (const float*)d_in[7];
    const float* b1b   = (const float*)d_in[8];
    const float* W1c   = (const float*)d_in[9];
    const float* b1c   = (const float*)d_in[10];
    const float* W2b   = (const float*)d_in[11];
    const float* b2b   = (const float*)d_in[12];
    const float* W2c   = (const float*)d_in[13];
    const float* b2c   = (const float*)d_in[14];
    const float* Wbp1  = (const float*)d_in[15];
    const float* bbp1  = (const float*)d_in[16];
    const float* gbp   = (const float*)d_in[17];
    const float* bebp  = (const float*)d_in[18];
    const float* Wbp2  = (const float*)d_in[19];
    const float* bbp2  = (const float*)d_in[20];
    const float* Wcp1  = (const float*)d_in[21];
    const float* bcp1  = (const float*)d_in[22];
    const float* gcp   = (const float*)d_in[23];
    const float* becp  = (const float*)d_in[24];
    const float* Wcp2  = (const float*)d_in[25];
    const float* bcp2  = (const float*)d_in[26];
    float* out = (float*)d_out;

    float *p_h, *p_xw;
    __half* p_pq;
    int *p_deg;
    cudaGetSymbolAddress((void**)&p_h, g_h);
    cudaGetSymbolAddress((void**)&p_xw, g_xw);
    cudaGetSymbolAddress((void**)&p_pq, g_pqh);
    cudaGetSymbolAddress((void**)&p_deg, g_degi);

    cudaFuncSetAttribute(k_mma, cudaFuncAttributeMaxDynamicSharedMemorySize, SMEM_MM);

    const int GB = (Nn + 127) / 128;   // 391 M-tiles
    const int EV4 = (Ee / 4) * 32;     // 4 edges per warp
    const int NW = Nn * 32;

    k_zero<<<(2 * Ee + 255) / 256, 256>>>((const int*)beam, out + 4 * Ee);   // 1
    k_cvt_deg<<<(2 * Ee + 255) / 256, 256>>>(beam, col);                     // 2
    k_encoder<<<GB, 128>>>(x, W_enc, b_enc);                                 // 3

    // GCN layer 1: xs_rel = dinv_rel * (bnaffine(h0) @ W1_rel)              // 4 <- profiled
    k_mma<<<dim3(GB, 2), 256, SMEM_MM>>>(p_h, W1b, W1c, W1b, W1b,
                                         p_xw, p_xw + NH, p_xw, p_xw,
                                         p_deg, p_deg + Nn,
                                         g_enc, be_enc, 0, Nn);
    k_scan<<<1, 1024>>>();                                                   // 5
    k_fill<<<(2 * Ee + 255) / 256, 256>>>();                                 // 6
    k_agg<<<(NW + 255) / 256, 256>>>(b1b, b1c, 1);                           // 7

    // GCN layer 2
    k_mma<<<dim3(GB, 2), 256, SMEM_MM>>>(p_h, W2b, W2c, W2b, W2b,            // 8
                                         p_xw, p_xw + NH, p_xw, p_xw,
                                         p_deg, p_deg + Nn,
                                         nullptr, nullptr, 0, Nn);
    k_agg<<<(NW + 255) / 256, 256>>>(b2b, b2c, 0);                           // 9

    // edge predictors: P/Q = h2 @ (top/bottom halves of Wbp1 / Wcp1), fp16 out
    k_mma<<<dim3(GB, 4), 256, SMEM_MM>>>(p_h, Wbp1, Wbp1 + Hh * Hh,          // 10
                                         Wcp1, Wcp1 + Hh * Hh,
                                         p_pq, p_pq + NH, p_pq + 2 * NH, p_pq + 3 * NH,
                                         nullptr, nullptr,
                                         nullptr, nullptr, 1, Nn);

    k_edge_stats<<<dim3(512, 2), 256>>>(p_pq, p_pq + NH, bbp1,               // 11
                                        p_pq + 2 * NH, p_pq + 3 * NH, bcp1);
    k_bn_pred<<<1, 128>>>(gbp, bebp, Wbp2, bbp2, gcp, becp, Wcp2, bcp2);     // 12
    k_pred<<<dim3((EV4 + 255) / 256, 2), 256>>>(p_pq, p_pq + NH, bbp1,       // 13
                                                p_pq + 2 * NH, p_pq + 3 * NH, bcp1, out);
}